// round 14
// baseline (speedup 1.0000x reference)
#include <cuda_runtime.h>
#include <math.h>

#define BATCH 32
#define SEQ 4096
#define HIDDEN 2048
#define ROUTE_H 256
#define NUM_EXPERTS 64
#define TOP_K 8
#define LN_EPS 1e-5f

#define NSPLIT 32                    // blocks per batch (also K-split for GEMV1)
#define SCHUNK (SEQ / NSPLIT)        // 128 seq rows per block
#define H4 (HIDDEN / 4)              // 512 float4 columns
#define KCHUNK (HIDDEN / NSPLIT)     // 64 hidden cols per GEMV1 slice
#define NTHR 256
#define NBLK (BATCH * NSPLIT)        // 1024 blocks; 7/SM x 8 warps = 56 <= 64

// Scratch (no cudaMalloc allowed). Zero-initialized at module load; counters
// are reset by the finale block each launch -> graph-replay safe.
__device__ float g_partial[NSPLIT * BATCH * HIDDEN];   // [sp][b][h] = 8 MB
__device__ float g_hpart[NSPLIT * BATCH * ROUTE_H];    // [ks][b][j] = 1 MB
__device__ unsigned int g_cnt1[BATCH];                 // pool-done election
__device__ unsigned int g_cnt2[BATCH];                 // gemv-done election

// ---------------------------------------------------------------------------
// ONE fused kernel. grid = 1024 blocks x 256 threads — all CTAs co-resident
// (7 blocks/SM x 8 warps = 56 warps, 32 regs) so per-batch spin-waits cannot
// deadlock. The finer grid keeps DRAM saturated through the final wave
// (pool-only benchmarking: 1024 blocks 87.5% DRAM vs 512 blocks 86.4%).
// Phase 1: pool partial for (b, sp): 2 float4 columns/thread over 128 rows.
// Phase 2: spin until batch b fully pooled, fold, 64-row GEMV1 K-slice.
// Phase 3: last finishing block of batch b runs LN + GELU + GEMV2 + top-8.
// All reduction orders fixed -> deterministic output.
// ---------------------------------------------------------------------------
__global__ void __launch_bounds__(NTHR) fused_router(
    const float* __restrict__ x,
    const float* __restrict__ W1, const float* __restrict__ b1,
    const float* __restrict__ ln_g, const float* __restrict__ ln_b,
    const float* __restrict__ W2, const float* __restrict__ b2,
    float* __restrict__ out)
{
    __shared__ float sh_fold[4][KCHUNK];
    __shared__ float sh_pool[KCHUNK];
    __shared__ unsigned int s_flag;

    int blk = blockIdx.x;
    int b   = blk / NSPLIT;
    int sp  = blk % NSPLIT;
    int t   = threadIdx.x;           // 0..255

    // ---------------- Phase 1: partial mean-pool ----------------
    // Thread owns float4 columns t and t+256: 2 independent chains, 256 loads.
    {
        const float4* base = (const float4*)(x) +
            ((size_t)b * SEQ + (size_t)sp * SCHUNK) * (size_t)H4;
        float4 accA = make_float4(0.f, 0.f, 0.f, 0.f);
        float4 accB = make_float4(0.f, 0.f, 0.f, 0.f);
#pragma unroll 4
        for (int s = 0; s < SCHUNK; s++) {
            float4 vA = __ldcs(&base[(size_t)s * H4 + t]);
            float4 vB = __ldcs(&base[(size_t)s * H4 + t + NTHR]);
            accA.x += vA.x; accA.y += vA.y; accA.z += vA.z; accA.w += vA.w;
            accB.x += vB.x; accB.y += vB.y; accB.z += vB.z; accB.w += vB.w;
        }
        float4* o = (float4*)(g_partial + ((size_t)sp * BATCH + b) * HIDDEN);
        o[t]        = accA;
        o[t + NTHR] = accB;
    }

    // ---------------- arrive + spin until batch b pooled ----------------
    __threadfence();                       // publish partials
    __syncthreads();
    if (t == 0) {
        atomicAdd(&g_cnt1[b], 1u);
        while (((volatile unsigned int*)g_cnt1)[b] < NSPLIT) { }
    }
    __syncthreads();
    __threadfence();                       // acquire all 32 partial slices

    // ---------------- Phase 2: GEMV1 K-slice for cols [sp*64, +64) ---------
    int i0 = sp * KCHUNK;

    // Fold 32 partials for 64 columns: thread (col = t&63, part = t>>6)
    // folds 8 partials in 2 chains; combine below. (L2-resident.)
    {
        int col  = t & (KCHUNK - 1);
        int part = t >> 6;                 // 0..3
        const float* p = g_partial +
            ((size_t)part * 8 * BATCH + b) * HIDDEN + i0 + col;
        float sA = 0.f, sB = 0.f;
#pragma unroll
        for (int q = 0; q < 4; q++) {
            sA += p[(size_t)(2 * q)     * BATCH * HIDDEN];
            sB += p[(size_t)(2 * q + 1) * BATCH * HIDDEN];
        }
        sh_fold[part][col] = sA + sB;
    }
    __syncthreads();
    if (t < KCHUNK) {
        sh_pool[t] = ((sh_fold[0][t] + sh_fold[1][t]) +
                      (sh_fold[2][t] + sh_fold[3][t])) * (1.0f / SEQ);
    }
    __syncthreads();

    // GEMV slice: 256 threads = 256 outputs, 64 rows each, 8 accumulators.
    {
        float a0 = 0.f, a1 = 0.f, a2 = 0.f, a3 = 0.f;
        float a4 = 0.f, a5 = 0.f, a6 = 0.f, a7 = 0.f;
#pragma unroll
        for (int r = 0; r < KCHUNK; r += 8) {
            const float* w = W1 + (size_t)(i0 + r) * ROUTE_H + t;
            a0 += sh_pool[r + 0] * w[0 * ROUTE_H];
            a1 += sh_pool[r + 1] * w[1 * ROUTE_H];
            a2 += sh_pool[r + 2] * w[2 * ROUTE_H];
            a3 += sh_pool[r + 3] * w[3 * ROUTE_H];
            a4 += sh_pool[r + 4] * w[4 * ROUTE_H];
            a5 += sh_pool[r + 5] * w[5 * ROUTE_H];
            a6 += sh_pool[r + 6] * w[6 * ROUTE_H];
            a7 += sh_pool[r + 7] * w[7 * ROUTE_H];
        }
        g_hpart[((size_t)sp * BATCH + b) * ROUTE_H + t] =
            ((a0 + a1) + (a2 + a3)) + ((a4 + a5) + (a6 + a7));
    }

    // ---------------- election: last GEMV block runs the finale ------------
    __threadfence();                       // publish h-partial slice
    __syncthreads();
    if (t == 0) {
        unsigned int old = atomicAdd(&g_cnt2[b], 1u);
        s_flag = (old == NSPLIT - 1) ? 1u : 0u;
    }
    __syncthreads();
    if (!s_flag) return;
    __threadfence();                       // acquire all 32 h-slices

    // ---------------- Phase 3: finale (all 256 threads) --------------------
    __shared__ float sh_h[ROUTE_H];
    __shared__ float sh_w1r[8], sh_w2r[8];
    __shared__ float sh_part[ROUTE_H];
    __shared__ float sh_logits[NUM_EXPERTS];

    int j    = t;
    int lane = t & 31;
    int warp = t >> 5;

    float h = 0.f;
#pragma unroll
    for (int k = 0; k < NSPLIT; k++)
        h += g_hpart[((size_t)k * BATCH + b) * ROUTE_H + j];
    h += b1[j];

    // LN reduce via warp shuffles (8 warps)
    float s1 = h, s2 = h * h;
#pragma unroll
    for (int o = 16; o > 0; o >>= 1) {
        s1 += __shfl_xor_sync(0xffffffffu, s1, o);
        s2 += __shfl_xor_sync(0xffffffffu, s2, o);
    }
    if (lane == 0) { sh_w1r[warp] = s1; sh_w2r[warp] = s2; }
    __syncthreads();
    float t1 = sh_w1r[lane & 7], t2 = sh_w2r[lane & 7];
#pragma unroll
    for (int o = 4; o > 0; o >>= 1) {
        t1 += __shfl_xor_sync(0xffffffffu, t1, o);
        t2 += __shfl_xor_sync(0xffffffffu, t2, o);
    }
    t1 = __shfl_sync(0xffffffffu, t1, 0);
    t2 = __shfl_sync(0xffffffffu, t2, 0);

    float mu  = t1 * (1.0f / ROUTE_H);
    float ms  = t2 * (1.0f / ROUTE_H);
    float inv = rsqrtf(ms - mu * mu + LN_EPS);
    h = (h - mu) * inv * ln_g[j] + ln_b[j];
    h = 0.5f * h * (1.0f + erff(h * 0.70710678118654752f));   // exact GELU
    sh_h[j] = h;
    __syncthreads();

    // GEMV2, K-split 4: 256 threads = 64 experts x 4 slices
    {
        int e   = j & (NUM_EXPERTS - 1);
        int ks2 = j >> 6;
        int r0  = ks2 * (ROUTE_H / 4);
        float a = 0.f;
#pragma unroll 8
        for (int i = 0; i < ROUTE_H / 4; i++)
            a += sh_h[r0 + i] * W2[(size_t)(r0 + i) * NUM_EXPERTS + e];
        sh_part[j] = a;
    }
    __syncthreads();
    if (j < NUM_EXPERTS) {
        sh_logits[j] = ((sh_part[j] + sh_part[j + 64]) +
                        (sh_part[j + 128] + sh_part[j + 192])) + b2[j];
        out[(size_t)b * NUM_EXPERTS + j] = 0.0f;   // d_out poisoned; zero first
    }
    __syncthreads();

    // top-8 + softmax + scatter (strict '>' = first-index tie-break, matching
    // jax.lax.top_k). Also reset counters for next graph replay.
    if (j == 0) {
        int   idx[TOP_K];
        float val[TOP_K];
        unsigned long long used = 0ull;
        for (int k = 0; k < TOP_K; k++) {
            float best = -INFINITY;
            int bi = 0;
            for (int e = 0; e < NUM_EXPERTS; e++) {
                if (!((used >> e) & 1ull) && sh_logits[e] > best) {
                    best = sh_logits[e]; bi = e;
                }
            }
            used |= (1ull << bi);
            idx[k] = bi;
            val[k] = best;
        }
        float mx = val[0];
        float denom = 0.f;
        float ex[TOP_K];
        for (int k = 0; k < TOP_K; k++) { ex[k] = expf(val[k] - mx); denom += ex[k]; }
        float rden = 1.0f / denom;
        for (int k = 0; k < TOP_K; k++)
            out[(size_t)b * NUM_EXPERTS + idx[k]] = ex[k] * rden;

        g_cnt1[b] = 0u;   // reset for next replay (all uses complete)
        g_cnt2[b] = 0u;
    }
}

// ---------------------------------------------------------------------------
extern "C" void kernel_launch(void* const* d_in, const int* in_sizes, int n_in,
                              void* d_out, int out_size) {
    const float* hs   = (const float*)d_in[0];
    const float* W1   = (const float*)d_in[1];
    const float* b1   = (const float*)d_in[2];
    const float* ln_g = (const float*)d_in[3];
    const float* ln_b = (const float*)d_in[4];
    const float* W2   = (const float*)d_in[5];
    const float* b2   = (const float*)d_in[6];
    // d_in[7] = top_k (hardcoded 8)

    float* out = (float*)d_out;

    fused_router<<<NBLK, NTHR>>>(hs, W1, b1, ln_g, ln_b, W2, b2, out);
}